// round 4
// baseline (speedup 1.0000x reference)
#include <cuda_runtime.h>
#include <cuda_bf16.h>

// ---------------------------------------------------------------------------
// Problem: out[b,s,o] = sum_d x[b,s,d]*W[o,d] + b[o] + ALPHA * z[b,s,o]
// where z = TT(x) is LINEAR in x:  z[.,o] = sum_d x[.,d] * E[d,o],
//   E[d,o] = sum_p3 A3[d,p3] * C1[o,p3]
//   A3 = core0 x core1 x core2 chain (m-side), C1 = core3 x core4 x core5 (n-side)
// => fold into W_total[o,d] = W[o,d] + ALPHA * E[d,o] and do ONE GEMM.
// ---------------------------------------------------------------------------

#define D_DIM 1024
#define M_ROWS (8 * 2048)   // B*S
#define ALPHA_F 16.0f

__device__ float g_A3[D_DIM * 8];      // [d][p3]
__device__ float g_C1[D_DIM * 8];      // [o][p3]  (pre-scaled by ALPHA)
__device__ float g_Wt[D_DIM * D_DIM];  // W_total[o][d]

// ---------------------------------------------------------------------------
// Kernel 1: build A3 (m-side chain) and C1 (n-side chain). One block.
// core0: (1,8,8)  [m1][p1]
// core1: (8,16,8) [p1][m2][p2]
// core2: (8,8,8)  [p2][m3][p3]
// core3: (8,8,8)  [p3][n1][p4]
// core4: (8,16,8) [p4][n2][p5]
// core5: (8,8,1)  [p5][n3]
// ---------------------------------------------------------------------------
__global__ void build_tt(const float* __restrict__ c0, const float* __restrict__ c1,
                         const float* __restrict__ c2, const float* __restrict__ c3,
                         const float* __restrict__ c4, const float* __restrict__ c5) {
    __shared__ float s1[1024], s2[512], s3[512], s4[1024];
    __shared__ float A1[64];     // [m1*8+p1]
    __shared__ float C3[64];     // [n3*8+p5]
    __shared__ float A2[1024];   // [(m2*8+m1)*8+p2]
    __shared__ float C2[1024];   // [(n2*8+n3)*8+p4]
    int t = threadIdx.x;

    for (int i = t; i < 1024; i += 256) s1[i] = c1[i];
    for (int i = t; i < 512;  i += 256) s2[i] = c2[i];
    for (int i = t; i < 512;  i += 256) s3[i] = c3[i];
    for (int i = t; i < 1024; i += 256) s4[i] = c4[i];
    if (t < 64) {
        A1[t] = c0[t];  // core0[0][m1][p1]
    } else if (t < 128) {
        int i = t - 64; int n3 = i >> 3, p5 = i & 7;
        C3[n3 * 8 + p5] = c5[p5 * 8 + n3];
    }
    __syncthreads();

    // A2[(m2*8+m1)][p2] = sum_p1 A1[m1][p1] * core1[p1][m2][p2]
    for (int i = t; i < 1024; i += 256) {
        int row = i >> 3, p2 = i & 7, m2 = row >> 3, m1 = row & 7;
        float s = 0.f;
        #pragma unroll
        for (int p1 = 0; p1 < 8; p1++) s += A1[m1 * 8 + p1] * s1[p1 * 128 + m2 * 8 + p2];
        A2[i] = s;
    }
    // C2[(n2*8+n3)][p4] = sum_p5 core4[p4][n2][p5] * C3[n3][p5]
    for (int i = t; i < 1024; i += 256) {
        int row = i >> 3, p4 = i & 7, n2 = row >> 3, n3 = row & 7;
        float s = 0.f;
        #pragma unroll
        for (int p5 = 0; p5 < 8; p5++) s += s4[p4 * 128 + n2 * 8 + p5] * C3[n3 * 8 + p5];
        C2[i] = s;
    }
    __syncthreads();

    // A3[d][p3] = sum_p2 A2[d&127][p2] * core2[p2][m3][p3],  d = m3*128 + rem
    for (int i = t; i < 8192; i += 256) {
        int d = i >> 3, p3 = i & 7, m3 = d >> 7, rem = d & 127;
        float s = 0.f;
        #pragma unroll
        for (int p2 = 0; p2 < 8; p2++) s += A2[rem * 8 + p2] * s2[p2 * 64 + m3 * 8 + p3];
        g_A3[i] = s;
    }
    // C1[o][p3] = ALPHA * sum_p4 core3[p3][n1][p4] * C2[o&127][p4],  o = n1*128 + rem
    for (int i = t; i < 8192; i += 256) {
        int o = i >> 3, p3 = i & 7, n1 = o >> 7, rem = o & 127;
        float s = 0.f;
        #pragma unroll
        for (int p4 = 0; p4 < 8; p4++) s += s3[p3 * 64 + n1 * 8 + p4] * C2[rem * 8 + p4];
        g_C1[i] = ALPHA_F * s;
    }
}

// ---------------------------------------------------------------------------
// Kernel 2: W_total[o][d] = W[o][d] + sum_p3 A3[d][p3]*C1[o][p3]
// One block per output row o. g_A3 (32KB) stays L2-resident.
// ---------------------------------------------------------------------------
__global__ void combine_w(const float* __restrict__ W) {
    int o = blockIdx.x;
    __shared__ float cl[8];
    if (threadIdx.x < 8) cl[threadIdx.x] = g_C1[o * 8 + threadIdx.x];
    __syncthreads();
    float c0 = cl[0], c1 = cl[1], c2 = cl[2], c3 = cl[3];
    float c4 = cl[4], c5 = cl[5], c6 = cl[6], c7 = cl[7];
    for (int d = threadIdx.x; d < D_DIM; d += 256) {
        const float4* a = (const float4*)&g_A3[d * 8];
        float4 a0 = a[0], a1 = a[1];
        float s = W[(size_t)o * D_DIM + d];
        s += a0.x * c0 + a0.y * c1 + a0.z * c2 + a0.w * c3;
        s += a1.x * c4 + a1.y * c5 + a1.z * c6 + a1.w * c7;
        g_Wt[(size_t)o * D_DIM + d] = s;
    }
}

// ---------------------------------------------------------------------------
// Kernel 3: SGEMM-NT  C[m][n] = sum_k A[m][k]*Wt[n][k] + bias[n]
// 128x128x8 tiles, 256 threads, 8x8 microtile, double-buffered smem.
// ---------------------------------------------------------------------------
#define BM 128
#define BN 128
#define BK 8
#define LDT 132   // padded leading dim (conflict-free transposed stores)

__global__ __launch_bounds__(256) void sgemm_nt(const float* __restrict__ A,
                                                const float* __restrict__ bias,
                                                float* __restrict__ C) {
    const int K = D_DIM, N = D_DIM;
    __shared__ float As[2][BK][LDT];
    __shared__ float Bs[2][BK][LDT];

    int tid = threadIdx.x;
    int bm = blockIdx.y * BM;
    int bn = blockIdx.x * BN;

    // global->smem load mapping: each thread one float4 per tile per operand
    int lr = tid >> 1;            // row within tile 0..127
    int lk = (tid & 1) * 4;       // k offset 0 or 4
    const float* Ap = A + (size_t)(bm + lr) * K + lk;
    const float* Bp = g_Wt + (size_t)(bn + lr) * K + lk;

    // compute mapping
    int tx = tid & 15;            // n-dir 0..15
    int ty = tid >> 4;            // m-dir 0..15

    float acc[8][8];
    #pragma unroll
    for (int i = 0; i < 8; i++)
        #pragma unroll
        for (int j = 0; j < 8; j++) acc[i][j] = 0.f;

    // prologue: tile 0
    float4 a4 = *(const float4*)Ap;
    float4 b4 = *(const float4*)Bp;
    As[0][lk + 0][lr] = a4.x; As[0][lk + 1][lr] = a4.y;
    As[0][lk + 2][lr] = a4.z; As[0][lk + 3][lr] = a4.w;
    Bs[0][lk + 0][lr] = b4.x; Bs[0][lk + 1][lr] = b4.y;
    Bs[0][lk + 2][lr] = b4.z; Bs[0][lk + 3][lr] = b4.w;
    __syncthreads();

    int buf = 0;
    for (int k0 = BK; k0 <= K; k0 += BK) {
        bool more = (k0 < K);
        if (more) {
            a4 = *(const float4*)(Ap + k0);
            b4 = *(const float4*)(Bp + k0);
        }
        #pragma unroll
        for (int kk = 0; kk < BK; kk++) {
            float4 ar0 = *(const float4*)&As[buf][kk][ty * 8];
            float4 ar1 = *(const float4*)&As[buf][kk][ty * 8 + 4];
            float4 br0 = *(const float4*)&Bs[buf][kk][tx * 8];
            float4 br1 = *(const float4*)&Bs[buf][kk][tx * 8 + 4];
            float ar[8] = {ar0.x, ar0.y, ar0.z, ar0.w, ar1.x, ar1.y, ar1.z, ar1.w};
            float br[8] = {br0.x, br0.y, br0.z, br0.w, br1.x, br1.y, br1.z, br1.w};
            #pragma unroll
            for (int i = 0; i < 8; i++)
                #pragma unroll
                for (int j = 0; j < 8; j++)
                    acc[i][j] += ar[i] * br[j];
        }
        if (more) {
            buf ^= 1;
            As[buf][lk + 0][lr] = a4.x; As[buf][lk + 1][lr] = a4.y;
            As[buf][lk + 2][lr] = a4.z; As[buf][lk + 3][lr] = a4.w;
            Bs[buf][lk + 0][lr] = b4.x; Bs[buf][lk + 1][lr] = b4.y;
            Bs[buf][lk + 2][lr] = b4.z; Bs[buf][lk + 3][lr] = b4.w;
            __syncthreads();
        }
    }

    // epilogue: add bias, store
    #pragma unroll
    for (int i = 0; i < 8; i++) {
        int row = bm + ty * 8 + i;
        #pragma unroll
        for (int j = 0; j < 8; j += 4) {
            int col = bn + tx * 8 + j;
            float4 v;
            v.x = acc[i][j + 0] + bias[col + 0];
            v.y = acc[i][j + 1] + bias[col + 1];
            v.z = acc[i][j + 2] + bias[col + 2];
            v.w = acc[i][j + 3] + bias[col + 3];
            *(float4*)&C[(size_t)row * N + col] = v;
        }
    }
}

// ---------------------------------------------------------------------------
extern "C" void kernel_launch(void* const* d_in, const int* in_sizes, int n_in,
                              void* d_out, int out_size) {
    const float* x  = (const float*)d_in[0];
    const float* W  = (const float*)d_in[1];
    const float* b  = (const float*)d_in[2];
    const float* c0 = (const float*)d_in[3];
    const float* c1 = (const float*)d_in[4];
    const float* c2 = (const float*)d_in[5];
    const float* c3 = (const float*)d_in[6];
    const float* c4 = (const float*)d_in[7];
    const float* c5 = (const float*)d_in[8];
    float* out = (float*)d_out;

    build_tt<<<1, 256>>>(c0, c1, c2, c3, c4, c5);
    combine_w<<<D_DIM, 256>>>(W);
    dim3 grid(D_DIM / BN, M_ROWS / BM);
    sgemm_nt<<<grid, 256>>>(x, b, out);
}

// round 6
// speedup vs baseline: 2.5025x; 2.5025x over previous
#include <cuda_runtime.h>
#include <cuda_bf16.h>
#include <cstdint>

// ---------------------------------------------------------------------------
// out = x @ (W + ALPHA*E)^T + b  folded into ONE GEMM on the HMMA path
// (tcgen05 is not available: harness PTX-compiles at .target sm_103, which
//  rejects all arch-conditional 'a' instructions; mma.sync/ldmatrix/cp.async
//  are baseline sm_80+ and work).
// fp32 emulated via bf16 split-2:  x = Ah+Al,  Wt = Bh+Bl
//   x*Wt ~= Ah*Bh + Al*Bh + Ah*Bl   (3 virtual K-segments, K'=3072)
// ---------------------------------------------------------------------------

#define D_DIM 1024
#define M_ROWS 16384
#define ALPHA_F 16.0f

__device__ float g_A3[D_DIM * 8];   // [d][p3]
__device__ float g_C1[D_DIM * 8];   // [o][p3] (pre-scaled by ALPHA)
__device__ __align__(16) __nv_bfloat16 g_A[(size_t)M_ROWS * 2048];  // [row][Ah|Al]
__device__ __align__(16) __nv_bfloat16 g_B2[(size_t)D_DIM * 2048];  // [o][Bh|Bl]

// ---------------------------------------------------------------------------
__device__ __forceinline__ uint32_t smem_u32(const void* p) {
    uint32_t a;
    asm("{ .reg .u64 t; cvta.to.shared.u64 t, %1; cvt.u32.u64 %0, t; }" : "=r"(a) : "l"(p));
    return a;
}
#define CP_ASYNC16(dst, src) \
    asm volatile("cp.async.cg.shared.global [%0], [%1], 16;" :: "r"(dst), "l"(src))
#define CP_COMMIT() asm volatile("cp.async.commit_group;" ::: "memory")
#define CP_WAIT(n)  asm volatile("cp.async.wait_group %0;" :: "n"(n) : "memory")

#define LDSM_X4(r0, r1, r2, r3, a) \
    asm volatile("ldmatrix.sync.aligned.m8n8.x4.shared.b16 {%0,%1,%2,%3}, [%4];" \
                 : "=r"(r0), "=r"(r1), "=r"(r2), "=r"(r3) : "r"(a))

#define MMA16816(d, a, b0, b1) \
    asm volatile("mma.sync.aligned.m16n8k16.row.col.f32.bf16.bf16.f32 " \
                 "{%0,%1,%2,%3}, {%4,%5,%6,%7}, {%8,%9}, {%0,%1,%2,%3};" \
                 : "+f"((d)[0]), "+f"((d)[1]), "+f"((d)[2]), "+f"((d)[3]) \
                 : "r"((a)[0]), "r"((a)[1]), "r"((a)[2]), "r"((a)[3]), \
                   "r"(b0), "r"(b1))

// ---------------------------------------------------------------------------
// Kernel 1: x -> [Ah | Al] bf16 split
// ---------------------------------------------------------------------------
__global__ void convert_x(const float* __restrict__ x) {
    size_t i = (size_t)blockIdx.x * 256 + threadIdx.x;   // float4 index
    float4 v = ((const float4*)x)[i];
    size_t r = i >> 8;
    int c = (int)(i & 255) * 4;
    __nv_bfloat16 h[4], l[4];
    float f[4] = {v.x, v.y, v.z, v.w};
    #pragma unroll
    for (int j = 0; j < 4; j++) {
        h[j] = __float2bfloat16_rn(f[j]);
        l[j] = __float2bfloat16_rn(f[j] - __bfloat162float(h[j]));
    }
    *(uint2*)&g_A[r * 2048 + c]        = *(uint2*)h;
    *(uint2*)&g_A[r * 2048 + 1024 + c] = *(uint2*)l;
}

// ---------------------------------------------------------------------------
// Kernel 2: TT core chains (block 0: m-side -> g_A3, block 1: n-side -> g_C1)
// ---------------------------------------------------------------------------
__global__ void build_tt(const float* __restrict__ c0, const float* __restrict__ c1,
                         const float* __restrict__ c2, const float* __restrict__ c3,
                         const float* __restrict__ c4, const float* __restrict__ c5) {
    __shared__ float sA[1024], sB[512], tmp[1024], first[64];
    int t = threadIdx.x;
    if (blockIdx.x == 0) {
        for (int i = t; i < 1024; i += 256) sA[i] = c1[i];
        for (int i = t; i < 512;  i += 256) sB[i] = c2[i];
        if (t < 64) first[t] = c0[t];
        __syncthreads();
        for (int i = t; i < 1024; i += 256) {
            int row = i >> 3, p2 = i & 7, m2 = row >> 3, m1 = row & 7;
            float s = 0.f;
            #pragma unroll
            for (int p1 = 0; p1 < 8; p1++) s += first[m1 * 8 + p1] * sA[p1 * 128 + m2 * 8 + p2];
            tmp[i] = s;
        }
        __syncthreads();
        for (int i = t; i < 8192; i += 256) {
            int d = i >> 3, p3 = i & 7, m3 = d >> 7, rem = d & 127;
            float s = 0.f;
            #pragma unroll
            for (int p2 = 0; p2 < 8; p2++) s += tmp[rem * 8 + p2] * sB[p2 * 64 + m3 * 8 + p3];
            g_A3[i] = s;
        }
    } else {
        for (int i = t; i < 1024; i += 256) sA[i] = c4[i];
        for (int i = t; i < 512;  i += 256) sB[i] = c3[i];
        if (t < 64) { int n3 = t >> 3, p5 = t & 7; first[n3 * 8 + p5] = c5[p5 * 8 + n3]; }
        __syncthreads();
        for (int i = t; i < 1024; i += 256) {
            int row = i >> 3, p4 = i & 7, n2 = row >> 3, n3 = row & 7;
            float s = 0.f;
            #pragma unroll
            for (int p5 = 0; p5 < 8; p5++) s += sA[p4 * 128 + n2 * 8 + p5] * first[n3 * 8 + p5];
            tmp[i] = s;
        }
        __syncthreads();
        for (int i = t; i < 8192; i += 256) {
            int o = i >> 3, p3 = i & 7, n1 = o >> 7, rem = o & 127;
            float s = 0.f;
            #pragma unroll
            for (int p4 = 0; p4 < 8; p4++) s += sB[p3 * 64 + n1 * 8 + p4] * tmp[rem * 8 + p4];
            g_C1[i] = ALPHA_F * s;
        }
    }
}

// ---------------------------------------------------------------------------
// Kernel 3: Wt = W + A3*C1^T, split -> g_B2 = [Bh | Bl]
// ---------------------------------------------------------------------------
__global__ void combine_w(const float* __restrict__ W) {
    int o = blockIdx.x;
    __shared__ float cl[8];
    if (threadIdx.x < 8) cl[threadIdx.x] = g_C1[o * 8 + threadIdx.x];
    __syncthreads();
    float c0 = cl[0], c1 = cl[1], c2 = cl[2], c3 = cl[3];
    float c4 = cl[4], c5 = cl[5], c6 = cl[6], c7 = cl[7];
    for (int d = threadIdx.x; d < D_DIM; d += 256) {
        const float4* a = (const float4*)&g_A3[d * 8];
        float4 a0 = a[0], a1 = a[1];
        float s = W[(size_t)o * D_DIM + d];
        s += a0.x * c0 + a0.y * c1 + a0.z * c2 + a0.w * c3;
        s += a1.x * c4 + a1.y * c5 + a1.z * c6 + a1.w * c7;
        __nv_bfloat16 hb = __float2bfloat16_rn(s);
        __nv_bfloat16 lb = __float2bfloat16_rn(s - __bfloat162float(hb));
        g_B2[(size_t)o * 2048 + d]        = hb;
        g_B2[(size_t)o * 2048 + 1024 + d] = lb;
    }
}

// ---------------------------------------------------------------------------
// Kernel 4: HMMA GEMM. CTA 128x128, BK=64 bf16 (128B rows), 4-stage cp.async.
// 8 warps: warp (wm=w>>2, wn=w&3) owns 64(m) x 32(n).
// Virtual K: 48 chunks = [Ah*Bh]x16 + [Al*Bh]x16 + [Ah*Bl]x16.
// SMEM per stage: A 16KB + B 16KB. XOR swizzle: col ^= (row&7)<<4 (on 16B units).
// ---------------------------------------------------------------------------
#define NSTAGE 4
#define STAGE_BYTES 32768
#define SMEM_TOTAL (NSTAGE * STAGE_BYTES)
#define NCHUNK 48

extern __shared__ __align__(1024) char smem[];

__global__ __launch_bounds__(256) void gemm_mma(const float* __restrict__ bias,
                                                float* __restrict__ out) {
    const int tid = threadIdx.x;
    const int bn = blockIdx.x * 128;
    const int bm = blockIdx.y * 128;
    const uint32_t sbase = smem_u32(smem);

    const int w = tid >> 5, l = tid & 31;
    const int wm = w >> 2, wn = w & 3;

    // ---- cp.async lane mapping: 8 vectors (4 A + 4 B) of 16B per thread ----
    uint32_t cp_dst[4];
    const __nv_bfloat16* cp_srcA[4];
    const __nv_bfloat16* cp_srcB[4];
    #pragma unroll
    for (int i = 0; i < 4; i++) {
        int v = tid + 256 * i;            // 0..1023
        int row = v >> 3, seg = v & 7;
        cp_dst[i]  = (uint32_t)(row * 128 + ((seg * 16) ^ ((row & 7) << 4)));
        cp_srcA[i] = g_A  + (size_t)(bm + row) * 2048 + seg * 8;
        cp_srcB[i] = g_B2 + (size_t)(bn + row) * 2048 + seg * 8;
    }

    // ---- ldmatrix lane address components ----
    // A: row = wm*64 + mf*16 + (l&15); col16 = ks*2 + (l>>4)   [16B units]
    const int arow = wm * 64 + (l & 15);
    const uint32_t axr = (uint32_t)((arow & 7) << 4);
    const uint32_t arb = (uint32_t)(arow * 128);
    const uint32_t ah16 = (uint32_t)((l >> 4) * 16);
    // B: row = wn*32 + nf2*16 + (l>>4)*8 + (l&7); colhalf = (l>>3)&1
    const int brow = wn * 32 + ((l >> 4) * 8) + (l & 7);
    const uint32_t bxr = (uint32_t)((l & 7) << 4);
    const uint32_t brb = (uint32_t)(brow * 128);
    const uint32_t bh16 = (uint32_t)(((l >> 3) & 1) * 16);

    float acc[4][4][4];
    #pragma unroll
    for (int i = 0; i < 4; i++)
        #pragma unroll
        for (int j = 0; j < 4; j++)
            #pragma unroll
            for (int k = 0; k < 4; k++) acc[i][j][k] = 0.f;

    // segment offsets (elements) per chunk: A [Ah|Al|Ah], B [Bh|Bh|Bl]
    auto issue_stage = [&](int t) {
        int seg = t >> 4, kk = (t & 15) * 64;
        int aoff = (seg == 1) ? 1024 + kk : kk;
        int boff = (seg == 2) ? 1024 + kk : kk;
        uint32_t sA = sbase + (t % NSTAGE) * STAGE_BYTES;
        uint32_t sB = sA + 16384;
        #pragma unroll
        for (int i = 0; i < 4; i++) CP_ASYNC16(sA + cp_dst[i], cp_srcA[i] + aoff);
        #pragma unroll
        for (int i = 0; i < 4; i++) CP_ASYNC16(sB + cp_dst[i], cp_srcB[i] + boff);
        CP_COMMIT();
    };

    issue_stage(0); issue_stage(1); issue_stage(2);

    for (int c = 0; c < NCHUNK; c++) {
        CP_WAIT(2);
        __syncthreads();
        if (c + 3 < NCHUNK) issue_stage(c + 3);

        const uint32_t sA = sbase + (c % NSTAGE) * STAGE_BYTES;
        const uint32_t sB = sA + 16384;
        #pragma unroll
        for (int ks = 0; ks < 4; ks++) {
            uint32_t a[4][4];
            uint32_t br[2][4];
            const uint32_t ac = (uint32_t)(ks * 32) + ah16;
            const uint32_t bc = (uint32_t)(ks * 32) + bh16;
            #pragma unroll
            for (int mf = 0; mf < 4; mf++)
                LDSM_X4(a[mf][0], a[mf][1], a[mf][2], a[mf][3],
                        sA + arb + mf * 2048 + (ac ^ axr));
            #pragma unroll
            for (int nf2 = 0; nf2 < 2; nf2++)
                LDSM_X4(br[nf2][0], br[nf2][1], br[nf2][2], br[nf2][3],
                        sB + brb + nf2 * 2048 + (bc ^ bxr));
            #pragma unroll
            for (int mf = 0; mf < 4; mf++)
                #pragma unroll
                for (int nf = 0; nf < 4; nf++)
                    MMA16816(acc[mf][nf], a[mf],
                             br[nf >> 1][(nf & 1) * 2], br[nf >> 1][(nf & 1) * 2 + 1]);
        }
    }

    // ---- epilogue: bias + store ----
    float2 bv[4];
    #pragma unroll
    for (int nf = 0; nf < 4; nf++) {
        int col = bn + wn * 32 + nf * 8 + (l & 3) * 2;
        bv[nf] = *(const float2*)(bias + col);
    }
    #pragma unroll
    for (int mf = 0; mf < 4; mf++) {
        int r0 = bm + wm * 64 + mf * 16 + (l >> 2);
        #pragma unroll
        for (int nf = 0; nf < 4; nf++) {
            int col = bn + wn * 32 + nf * 8 + (l & 3) * 2;
            float2 v0 = {acc[mf][nf][0] + bv[nf].x, acc[mf][nf][1] + bv[nf].y};
            float2 v1 = {acc[mf][nf][2] + bv[nf].x, acc[mf][nf][3] + bv[nf].y};
            *(float2*)(out + (size_t)r0 * D_DIM + col) = v0;
            *(float2*)(out + (size_t)(r0 + 8) * D_DIM + col) = v1;
        }
    }
}

// ---------------------------------------------------------------------------
extern "C" void kernel_launch(void* const* d_in, const int* in_sizes, int n_in,
                              void* d_out, int out_size) {
    const float* x  = (const float*)d_in[0];
    const float* W  = (const float*)d_in[1];
    const float* b  = (const float*)d_in[2];
    const float* c0 = (const float*)d_in[3];
    const float* c1 = (const float*)d_in[4];
    const float* c2 = (const float*)d_in[5];
    const float* c3 = (const float*)d_in[6];
    const float* c4 = (const float*)d_in[7];
    const float* c5 = (const float*)d_in[8];
    float* out = (float*)d_out;

    cudaFuncSetAttribute(gemm_mma, cudaFuncAttributeMaxDynamicSharedMemorySize, SMEM_TOTAL);

    convert_x<<<(M_ROWS * D_DIM / 4) / 256, 256>>>(x);
    build_tt<<<2, 256>>>(c0, c1, c2, c3, c4, c5);
    combine_w<<<D_DIM, 256>>>(W);
    dim3 grid(D_DIM / 128, M_ROWS / 128);
    gemm_mma<<<grid, 256, SMEM_TOTAL>>>(b, out);
}

// round 10
// speedup vs baseline: 2.7966x; 1.1175x over previous
#include <cuda_runtime.h>
#include <cuda_bf16.h>
#include <cstdint>

// ---------------------------------------------------------------------------
// out = x @ (W + ALPHA*E)^T + b  folded into ONE GEMM on the HMMA path
// (tcgen05 unavailable: harness compiles PTX at .target sm_103 — no 'a').
// fp32 emulated via bf16 split-2:  x = Ah+Al,  Wt = Bh+Bl
//   x*Wt ~= Ah*Bh + Al*Bh + Ah*Bl   (3 virtual K-segments, K'=3072)
// R7 change: 3-stage pipeline (96KB smem) + launch_bounds(256,2) -> 2 CTA/SM.
// ---------------------------------------------------------------------------

#define D_DIM 1024
#define M_ROWS 16384
#define ALPHA_F 16.0f

__device__ float g_A3[D_DIM * 8];   // [d][p3]
__device__ float g_C1[D_DIM * 8];   // [o][p3] (pre-scaled by ALPHA)
__device__ __align__(16) __nv_bfloat16 g_A[(size_t)M_ROWS * 2048];  // [row][Ah|Al]
__device__ __align__(16) __nv_bfloat16 g_B2[(size_t)D_DIM * 2048];  // [o][Bh|Bl]

// ---------------------------------------------------------------------------
__device__ __forceinline__ uint32_t smem_u32(const void* p) {
    uint32_t a;
    asm("{ .reg .u64 t; cvta.to.shared.u64 t, %1; cvt.u32.u64 %0, t; }" : "=r"(a) : "l"(p));
    return a;
}
#define CP_ASYNC16(dst, src) \
    asm volatile("cp.async.cg.shared.global [%0], [%1], 16;" :: "r"(dst), "l"(src))
#define CP_COMMIT() asm volatile("cp.async.commit_group;" ::: "memory")
#define CP_WAIT(n)  asm volatile("cp.async.wait_group %0;" :: "n"(n) : "memory")

#define LDSM_X4(r0, r1, r2, r3, a) \
    asm volatile("ldmatrix.sync.aligned.m8n8.x4.shared.b16 {%0,%1,%2,%3}, [%4];" \
                 : "=r"(r0), "=r"(r1), "=r"(r2), "=r"(r3) : "r"(a))

#define MMA16816(d, a, b0, b1) \
    asm volatile("mma.sync.aligned.m16n8k16.row.col.f32.bf16.bf16.f32 " \
                 "{%0,%1,%2,%3}, {%4,%5,%6,%7}, {%8,%9}, {%0,%1,%2,%3};" \
                 : "+f"((d)[0]), "+f"((d)[1]), "+f"((d)[2]), "+f"((d)[3]) \
                 : "r"((a)[0]), "r"((a)[1]), "r"((a)[2]), "r"((a)[3]), \
                   "r"(b0), "r"(b1))

// ---------------------------------------------------------------------------
// Kernel 1: x -> [Ah | Al] bf16 split
// ---------------------------------------------------------------------------
__global__ void convert_x(const float* __restrict__ x) {
    size_t i = (size_t)blockIdx.x * 256 + threadIdx.x;   // float4 index
    float4 v = ((const float4*)x)[i];
    size_t r = i >> 8;
    int c = (int)(i & 255) * 4;
    __nv_bfloat16 h[4], l[4];
    float f[4] = {v.x, v.y, v.z, v.w};
    #pragma unroll
    for (int j = 0; j < 4; j++) {
        h[j] = __float2bfloat16_rn(f[j]);
        l[j] = __float2bfloat16_rn(f[j] - __bfloat162float(h[j]));
    }
    *(uint2*)&g_A[r * 2048 + c]        = *(uint2*)h;
    *(uint2*)&g_A[r * 2048 + 1024 + c] = *(uint2*)l;
}

// ---------------------------------------------------------------------------
// Kernel 2: TT core chains (block 0: m-side -> g_A3, block 1: n-side -> g_C1)
// ---------------------------------------------------------------------------
__global__ void build_tt(const float* __restrict__ c0, const float* __restrict__ c1,
                         const float* __restrict__ c2, const float* __restrict__ c3,
                         const float* __restrict__ c4, const float* __restrict__ c5) {
    __shared__ float sA[1024], sB[512], tmp[1024], first[64];
    int t = threadIdx.x;
    if (blockIdx.x == 0) {
        for (int i = t; i < 1024; i += 256) sA[i] = c1[i];
        for (int i = t; i < 512;  i += 256) sB[i] = c2[i];
        if (t < 64) first[t] = c0[t];
        __syncthreads();
        for (int i = t; i < 1024; i += 256) {
            int row = i >> 3, p2 = i & 7, m2 = row >> 3, m1 = row & 7;
            float s = 0.f;
            #pragma unroll
            for (int p1 = 0; p1 < 8; p1++) s += first[m1 * 8 + p1] * sA[p1 * 128 + m2 * 8 + p2];
            tmp[i] = s;
        }
        __syncthreads();
        for (int i = t; i < 8192; i += 256) {
            int d = i >> 3, p3 = i & 7, m3 = d >> 7, rem = d & 127;
            float s = 0.f;
            #pragma unroll
            for (int p2 = 0; p2 < 8; p2++) s += tmp[rem * 8 + p2] * sB[p2 * 64 + m3 * 8 + p3];
            g_A3[i] = s;
        }
    } else {
        for (int i = t; i < 1024; i += 256) sA[i] = c4[i];
        for (int i = t; i < 512;  i += 256) sB[i] = c3[i];
        if (t < 64) { int n3 = t >> 3, p5 = t & 7; first[n3 * 8 + p5] = c5[p5 * 8 + n3]; }
        __syncthreads();
        for (int i = t; i < 1024; i += 256) {
            int row = i >> 3, p4 = i & 7, n2 = row >> 3, n3 = row & 7;
            float s = 0.f;
            #pragma unroll
            for (int p5 = 0; p5 < 8; p5++) s += sA[p4 * 128 + n2 * 8 + p5] * first[n3 * 8 + p5];
            tmp[i] = s;
        }
        __syncthreads();
        for (int i = t; i < 8192; i += 256) {
            int o = i >> 3, p3 = i & 7, n1 = o >> 7, rem = o & 127;
            float s = 0.f;
            #pragma unroll
            for (int p4 = 0; p4 < 8; p4++) s += sB[p3 * 64 + n1 * 8 + p4] * tmp[rem * 8 + p4];
            g_C1[i] = ALPHA_F * s;
        }
    }
}

// ---------------------------------------------------------------------------
// Kernel 3: Wt = W + A3*C1^T, split -> g_B2 = [Bh | Bl]
// ---------------------------------------------------------------------------
__global__ void combine_w(const float* __restrict__ W) {
    int o = blockIdx.x;
    __shared__ float cl[8];
    if (threadIdx.x < 8) cl[threadIdx.x] = g_C1[o * 8 + threadIdx.x];
    __syncthreads();
    float c0 = cl[0], c1 = cl[1], c2 = cl[2], c3 = cl[3];
    float c4 = cl[4], c5 = cl[5], c6 = cl[6], c7 = cl[7];
    for (int d = threadIdx.x; d < D_DIM; d += 256) {
        const float4* a = (const float4*)&g_A3[d * 8];
        float4 a0 = a[0], a1 = a[1];
        float s = W[(size_t)o * D_DIM + d];
        s += a0.x * c0 + a0.y * c1 + a0.z * c2 + a0.w * c3;
        s += a1.x * c4 + a1.y * c5 + a1.z * c6 + a1.w * c7;
        __nv_bfloat16 hb = __float2bfloat16_rn(s);
        __nv_bfloat16 lb = __float2bfloat16_rn(s - __bfloat162float(hb));
        g_B2[(size_t)o * 2048 + d]        = hb;
        g_B2[(size_t)o * 2048 + 1024 + d] = lb;
    }
}

// ---------------------------------------------------------------------------
// Kernel 4: HMMA GEMM. CTA 128x128, BK=64 bf16, 3-stage cp.async, 2 CTA/SM.
// 8 warps: warp (wm=w>>2, wn=w&3) owns 64(m) x 32(n).
// Virtual K: 48 chunks = [Ah*Bh]x16 + [Al*Bh]x16 + [Ah*Bl]x16.
// XOR swizzle: col16B ^= (row&7)<<4.
// ---------------------------------------------------------------------------
#define NSTAGE 3
#define STAGE_BYTES 32768
#define SMEM_TOTAL (NSTAGE * STAGE_BYTES)
#define NCHUNK 48

extern __shared__ __align__(1024) char smem[];

__global__ __launch_bounds__(256, 2) void gemm_mma(const float* __restrict__ bias,
                                                   float* __restrict__ out) {
    const int tid = threadIdx.x;
    const int bn = blockIdx.x * 128;
    const int bm = blockIdx.y * 128;
    const uint32_t sbase = smem_u32(smem);

    const int w = tid >> 5, l = tid & 31;
    const int wm = w >> 2, wn = w & 3;

    // ---- cp.async lane mapping: 8 vectors (4 A + 4 B) of 16B per thread ----
    uint32_t cp_dst[4];
    const __nv_bfloat16* cp_srcA[4];
    const __nv_bfloat16* cp_srcB[4];
    #pragma unroll
    for (int i = 0; i < 4; i++) {
        int v = tid + 256 * i;            // 0..1023
        int row = v >> 3, seg = v & 7;
        cp_dst[i]  = (uint32_t)(row * 128 + ((seg * 16) ^ ((row & 7) << 4)));
        cp_srcA[i] = g_A  + (size_t)(bm + row) * 2048 + seg * 8;
        cp_srcB[i] = g_B2 + (size_t)(bn + row) * 2048 + seg * 8;
    }

    // ---- ldmatrix lane address components ----
    const int arow = wm * 64 + (l & 15);
    const uint32_t axr = (uint32_t)((arow & 7) << 4);
    const uint32_t arb = (uint32_t)(arow * 128);
    const uint32_t ah16 = (uint32_t)((l >> 4) * 16);
    const int brow = wn * 32 + ((l >> 4) * 8) + (l & 7);
    const uint32_t bxr = (uint32_t)((l & 7) << 4);
    const uint32_t brb = (uint32_t)(brow * 128);
    const uint32_t bh16 = (uint32_t)(((l >> 3) & 1) * 16);

    float acc[4][4][4];
    #pragma unroll
    for (int i = 0; i < 4; i++)
        #pragma unroll
        for (int j = 0; j < 4; j++)
            #pragma unroll
            for (int k = 0; k < 4; k++) acc[i][j][k] = 0.f;

    // segment offsets (elements) per chunk: A [Ah|Al|Ah], B [Bh|Bh|Bl]
    auto issue_stage = [&](int t) {
        int seg = t >> 4, kk = (t & 15) * 64;
        int aoff = (seg == 1) ? 1024 + kk : kk;
        int boff = (seg == 2) ? 1024 + kk : kk;
        uint32_t sA = sbase + (t % NSTAGE) * STAGE_BYTES;
        uint32_t sB = sA + 16384;
        #pragma unroll
        for (int i = 0; i < 4; i++) CP_ASYNC16(sA + cp_dst[i], cp_srcA[i] + aoff);
        #pragma unroll
        for (int i = 0; i < 4; i++) CP_ASYNC16(sB + cp_dst[i], cp_srcB[i] + boff);
        CP_COMMIT();
    };

    issue_stage(0); issue_stage(1);

    for (int c = 0; c < NCHUNK; c++) {
        CP_WAIT(1);
        __syncthreads();
        if (c + 2 < NCHUNK) issue_stage(c + 2);

        const uint32_t sA = sbase + (c % NSTAGE) * STAGE_BYTES;
        const uint32_t sB = sA + 16384;
        #pragma unroll
        for (int ks = 0; ks < 4; ks++) {
            uint32_t a[4][4];
            uint32_t br[2][4];
            const uint32_t ac = (uint32_t)(ks * 32) + ah16;
            const uint32_t bc = (uint32_t)(ks * 32) + bh16;
            #pragma unroll
            for (int mf = 0; mf < 4; mf++)
                LDSM_X4(a[mf][0], a[mf][1], a[mf][2], a[mf][3],
                        sA + arb + mf * 2048 + (ac ^ axr));
            #pragma unroll
            for (int nf2 = 0; nf2 < 2; nf2++)
                LDSM_X4(br[nf2][0], br[nf2][1], br[nf2][2], br[nf2][3],
                        sB + brb + nf2 * 2048 + (bc ^ bxr));
            #pragma unroll
            for (int mf = 0; mf < 4; mf++)
                #pragma unroll
                for (int nf = 0; nf < 4; nf++)
                    MMA16816(acc[mf][nf], a[mf],
                             br[nf >> 1][(nf & 1) * 2], br[nf >> 1][(nf & 1) * 2 + 1]);
        }
        __syncthreads();
    }

    // ---- epilogue: bias + store ----
    float2 bv[4];
    #pragma unroll
    for (int nf = 0; nf < 4; nf++) {
        int col = bn + wn * 32 + nf * 8 + (l & 3) * 2;
        bv[nf] = *(const float2*)(bias + col);
    }
    #pragma unroll
    for (int mf = 0; mf < 4; mf++) {
        int r0 = bm + wm * 64 + mf * 16 + (l >> 2);
        #pragma unroll
        for (int nf = 0; nf < 4; nf++) {
            int col = bn + wn * 32 + nf * 8 + (l & 3) * 2;
            float2 v0 = {acc[mf][nf][0] + bv[nf].x, acc[mf][nf][1] + bv[nf].y};
            float2 v1 = {acc[mf][nf][2] + bv[nf].x, acc[mf][nf][3] + bv[nf].y};
            *(float2*)(out + (size_t)r0 * D_DIM + col) = v0;
            *(float2*)(out + (size_t)(r0 + 8) * D_DIM + col) = v1;
        }
    }
}

// ---------------------------------------------------------------------------
extern "C" void kernel_launch(void* const* d_in, const int* in_sizes, int n_in,
                              void* d_out, int out_size) {
    const float* x  = (const float*)d_in[0];
    const float* W  = (const float*)d_in[1];
    const float* b  = (const float*)d_in[2];
    const float* c0 = (const float*)d_in[3];
    const float* c1 = (const float*)d_in[4];
    const float* c2 = (const float*)d_in[5];
    const float* c3 = (const float*)d_in[6];
    const float* c4 = (const float*)d_in[7];
    const float* c5 = (const float*)d_in[8];
    float* out = (float*)d_out;

    cudaFuncSetAttribute(gemm_mma, cudaFuncAttributeMaxDynamicSharedMemorySize, SMEM_TOTAL);

    convert_x<<<(M_ROWS * D_DIM / 4) / 256, 256>>>(x);
    build_tt<<<2, 256>>>(c0, c1, c2, c3, c4, c5);
    combine_w<<<D_DIM, 256>>>(W);
    dim3 grid(D_DIM / 128, M_ROWS / 128);
    gemm_mma<<<grid, 256, SMEM_TOTAL>>>(b, out);
}